// round 1
// baseline (speedup 1.0000x reference)
#include <cuda_runtime.h>
#include <math.h>
#include <stdint.h>

#define NR 3200
#define NA 320
#define TD 512
#define DD 128
#define H  128
#define B  8

// ---------------- scratch (device globals; no allocations allowed) ----------
__device__ float g_tf[NR * H];
__device__ float g_df[NA * H];
__device__ int   g_as[B];         // atom range start per segment
__device__ int   g_ae[B];         // atom range end (exclusive)
__device__ int   g_dmin_bits[B];  // float bits, nonnegative -> int order == float order
__device__ int   g_dmax_bits[B];
__device__ float g_dminf[B];
__device__ float g_invden[B];

// ---------------- 1. reset per-launch atomics --------------------------------
__global__ void k_init() {
    int b = threadIdx.x;
    if (b < B) {
        g_as[b] = NA;
        g_ae[b] = 0;
        g_dmin_bits[b] = 0x7F800000; // +inf
        g_dmax_bits[b] = 0;          // 0.0f (distances are >= 0)
    }
}

// ---------------- 2. contiguous atom range per segment (seg_atom sorted) -----
__global__ void k_ranges(const int* __restrict__ seg_atom) {
    int j = blockIdx.x * blockDim.x + threadIdx.x;
    if (j < NA) {
        int s = seg_atom[j];
        atomicMin(&g_as[s], j);
        atomicMax(&g_ae[s], j + 1);
    }
}

// ---------------- 3. tf = target_feature @ Wt + bt  [NR,TD]x[TD,H] ----------
// 8 rows per block, 128 threads (one per output column h).
__global__ void __launch_bounds__(128) k_tf(const float* __restrict__ A,
                                            const float* __restrict__ W,
                                            const float* __restrict__ bias) {
    __shared__ float sA[8][TD]; // 16 KB
    const int i0 = blockIdx.x * 8;
    for (int idx = threadIdx.x; idx < 8 * TD; idx += 128)
        sA[idx >> 9][idx & (TD - 1)] = A[(size_t)i0 * TD + idx];
    __syncthreads();

    const int h = threadIdx.x;
    float acc[8] = {0.f, 0.f, 0.f, 0.f, 0.f, 0.f, 0.f, 0.f};
    #pragma unroll 4
    for (int k = 0; k < TD; k++) {
        float w = W[k * H + h];
        #pragma unroll
        for (int r = 0; r < 8; r++) acc[r] = fmaf(sA[r][k], w, acc[r]);
    }
    float bb = bias[h];
    #pragma unroll
    for (int r = 0; r < 8; r++) g_tf[(i0 + r) * H + h] = acc[r] + bb;
}

// ---------------- 4. df = drug_feature @ Wd + bd  [NA,DD]x[DD,H] -------------
__global__ void __launch_bounds__(128) k_df(const float* __restrict__ A,
                                            const float* __restrict__ W,
                                            const float* __restrict__ bias) {
    __shared__ float sA[8][DD];
    const int i0 = blockIdx.x * 8;
    for (int idx = threadIdx.x; idx < 8 * DD; idx += 128)
        sA[idx >> 7][idx & (DD - 1)] = A[(size_t)i0 * DD + idx];
    __syncthreads();

    const int h = threadIdx.x;
    float acc[8] = {0.f, 0.f, 0.f, 0.f, 0.f, 0.f, 0.f, 0.f};
    #pragma unroll 4
    for (int k = 0; k < DD; k++) {
        float w = W[k * H + h];
        #pragma unroll
        for (int r = 0; r < 8; r++) acc[r] = fmaf(sA[r][k], w, acc[r]);
    }
    float bb = bias[h];
    #pragma unroll
    for (int r = 0; r < 8; r++) g_df[(i0 + r) * H + h] = acc[r] + bb;
}

// ---------------- 5. per-segment distance min/max ----------------------------
__global__ void __launch_bounds__(128) k_dist(const float* __restrict__ tpos,
                                              const float* __restrict__ dpos,
                                              const int* __restrict__ seg_res) {
    const int i = blockIdx.x;
    const int b = seg_res[i];
    const int as = g_as[b], ae = g_ae[b];
    if (ae <= as) return;

    const float px = tpos[3 * i], py = tpos[3 * i + 1], pz = tpos[3 * i + 2];
    float mn = INFINITY, mx = 0.0f;
    for (int j = as + (int)threadIdx.x; j < ae; j += 128) {
        float dx = px - dpos[3 * j];
        float dy = py - dpos[3 * j + 1];
        float dz = pz - dpos[3 * j + 2];
        float d = sqrtf(dx * dx + dy * dy + dz * dz);
        mn = fminf(mn, d);
        mx = fmaxf(mx, d);
    }
    #pragma unroll
    for (int o = 16; o; o >>= 1) {
        mn = fminf(mn, __shfl_xor_sync(0xFFFFFFFFu, mn, o));
        mx = fmaxf(mx, __shfl_xor_sync(0xFFFFFFFFu, mx, o));
    }
    __shared__ float smn[4], smx[4];
    const int w = threadIdx.x >> 5;
    if ((threadIdx.x & 31) == 0) { smn[w] = mn; smx[w] = mx; }
    __syncthreads();
    if (threadIdx.x == 0) {
        #pragma unroll
        for (int k = 1; k < 4; k++) { mn = fminf(mn, smn[k]); mx = fmaxf(mx, smx[k]); }
        atomicMin(&g_dmin_bits[b], __float_as_int(mn));
        atomicMax(&g_dmax_bits[b], __float_as_int(mx));
    }
}

// ---------------- 6. finalize dmin / 1/denom ----------------------------------
__global__ void k_final() {
    int b = threadIdx.x;
    if (b < B) {
        float dmin = __int_as_float(g_dmin_bits[b]);
        float dmax = __int_as_float(g_dmax_bits[b]);
        if (!isfinite(dmin)) dmin = 0.0f; // empty segment (dnorm unused then)
        float den = (dmax > dmin) ? (dmax - dmin) : 1.0f;
        g_dminf[b] = dmin;
        g_invden[b] = 1.0f / den;
    }
}

// ---------------- 7. main streaming kernel ------------------------------------
// One block per residue row: 320*128 floats = 10240 float4.
// Zero stripes [0,as) and [ae,NA); tanh stripe [as,ae).
__global__ void __launch_bounds__(256) k_main(const int* __restrict__ seg_res,
                                              const float* __restrict__ tpos,
                                              const float* __restrict__ dpos,
                                              float* __restrict__ out) {
    const int i = blockIdx.x;
    const int b = seg_res[i];
    const int as = g_as[b], ae = g_ae[b];

    __shared__ float s_tf[H];
    __shared__ float s_dn[NA];

    if (threadIdx.x < H) s_tf[threadIdx.x] = g_tf[i * H + threadIdx.x];

    const float px = tpos[3 * i], py = tpos[3 * i + 1], pz = tpos[3 * i + 2];
    const float dmin = g_dminf[b], inv = g_invden[b];
    for (int j = as + (int)threadIdx.x; j < ae; j += 256) {
        float dx = px - dpos[3 * j];
        float dy = py - dpos[3 * j + 1];
        float dz = pz - dpos[3 * j + 2];
        s_dn[j - as] = (sqrtf(dx * dx + dy * dy + dz * dz) - dmin) * inv;
    }
    __syncthreads();

    float4* out4 = reinterpret_cast<float4*>(out) + (size_t)i * (NA * H / 4);
    const float4 z4 = make_float4(0.f, 0.f, 0.f, 0.f);

    // left zero stripe: j in [0, as)
    const int nl = as * (H / 4);
    for (int idx = threadIdx.x; idx < nl; idx += 256) out4[idx] = z4;

    // right zero stripe: j in [ae, NA)
    const int nr = (NA - ae) * (H / 4);
    float4* outr = out4 + ae * (H / 4);
    for (int idx = threadIdx.x; idx < nr; idx += 256) outr[idx] = z4;

    // middle: tanh(tf - df + dnorm)
    const int nm = (ae - as) * (H / 4);
    const float4* df4 = reinterpret_cast<const float4*>(g_df);
    const float4* tf4 = reinterpret_cast<const float4*>(s_tf);
    float4* outm = out4 + as * (H / 4);
    for (int idx = threadIdx.x; idx < nm; idx += 256) {
        const int jo = idx >> 5;       // local atom index
        const int q  = idx & 31;       // float4 chunk within H
        const float dn = s_dn[jo];
        const float4 t = tf4[q];
        const float4 d = df4[(size_t)(as + jo) * (H / 4) + q];
        float4 r;
        r.x = tanhf(t.x - d.x + dn);
        r.y = tanhf(t.y - d.y + dn);
        r.z = tanhf(t.z - d.z + dn);
        r.w = tanhf(t.w - d.w + dn);
        outm[idx] = r;
    }
}

// ---------------- launch -------------------------------------------------------
extern "C" void kernel_launch(void* const* d_in, const int* in_sizes, int n_in,
                              void* d_out, int out_size) {
    const float* target_feature = (const float*)d_in[0];
    const float* drug_feature   = (const float*)d_in[1];
    const float* target_pos     = (const float*)d_in[2];
    const float* drug_pos       = (const float*)d_in[3];
    const float* Wt             = (const float*)d_in[4];
    const float* bt             = (const float*)d_in[5];
    const float* Wd             = (const float*)d_in[6];
    const float* bd             = (const float*)d_in[7];
    const int*   seg_res        = (const int*)d_in[8];
    const int*   seg_atom       = (const int*)d_in[9];
    float* out = (float*)d_out;

    k_init<<<1, 32>>>();
    k_ranges<<<(NA + 255) / 256, 256>>>(seg_atom);
    k_tf<<<NR / 8, 128>>>(target_feature, Wt, bt);
    k_df<<<NA / 8, 128>>>(drug_feature, Wd, bd);
    k_dist<<<NR, 128>>>(target_pos, drug_pos, seg_res);
    k_final<<<1, B>>>();
    k_main<<<NR, 256>>>(seg_res, target_pos, drug_pos, out);
}

// round 2
// speedup vs baseline: 1.3679x; 1.3679x over previous
#include <cuda_runtime.h>
#include <math.h>
#include <stdint.h>

#define NR 3200
#define NA 320
#define TD 512
#define DD 128
#define H  128
#define B  8

#define NTF 200   // tf GEMM blocks, 16 rows each
#define NDF 40    // df GEMM blocks, 8 rows each

// ---------------- scratch (device globals) ----------------------------------
__device__ float g_tf[NR * H];
__device__ float g_df[NA * H];
__device__ float g_rowmin[NR];
__device__ float g_rowmax[NR];
__device__ int   g_as[B];
__device__ int   g_ae[B];
__device__ float g_dminf[B];
__device__ float g_invden[B];
__device__ int   g_count = 0;   // last-block counter, self-resetting

__device__ __forceinline__ int lowerb(const int* __restrict__ a, int n, int key) {
    int lo = 0, hi = n;
    while (lo < hi) { int m = (lo + hi) >> 1; if (a[m] < key) lo = m + 1; else hi = m; }
    return lo;
}

// ---------------- Kernel A: tf GEMM + df GEMM + row dist min/max + reduce ----
__global__ void __launch_bounds__(256) kA(const float* __restrict__ tfeat,
                                          const float* __restrict__ Wt,
                                          const float* __restrict__ bt,
                                          const float* __restrict__ dfeat,
                                          const float* __restrict__ Wd,
                                          const float* __restrict__ bd,
                                          const float* __restrict__ tpos,
                                          const float* __restrict__ dpos,
                                          const int* __restrict__ seg_res,
                                          const int* __restrict__ seg_atom) {
    __shared__ float sA[16 * TD];          // 32 KB (df path uses a prefix)
    __shared__ int   s_mn[B], s_mx[B], s_as[B], s_ae[B];
    __shared__ bool  isLast;

    const int t = threadIdx.x;
    const int w = t >> 5, lane = t & 31;

    if (blockIdx.x < NTF) {
        // ---------------- tf GEMM: 16 rows x 128 cols ----------------
        const int i0 = blockIdx.x * 16;
        const float4* src = reinterpret_cast<const float4*>(tfeat + (size_t)i0 * TD);
        float4* dst = reinterpret_cast<float4*>(sA);
        #pragma unroll
        for (int idx = t; idx < 16 * TD / 4; idx += 256) dst[idx] = src[idx];
        __syncthreads();

        const float* a0 = sA + (2 * w) * TD;
        const float* a1 = sA + (2 * w + 1) * TD;
        const float4* W4 = reinterpret_cast<const float4*>(Wt);  // [TD][32] of float4
        float4 acc0 = make_float4(0.f, 0.f, 0.f, 0.f);
        float4 acc1 = make_float4(0.f, 0.f, 0.f, 0.f);
        #pragma unroll 8
        for (int k = 0; k < TD; k++) {
            float4 wv = W4[k * 32 + lane];
            float x0 = a0[k], x1 = a1[k];
            acc0.x = fmaf(x0, wv.x, acc0.x); acc0.y = fmaf(x0, wv.y, acc0.y);
            acc0.z = fmaf(x0, wv.z, acc0.z); acc0.w = fmaf(x0, wv.w, acc0.w);
            acc1.x = fmaf(x1, wv.x, acc1.x); acc1.y = fmaf(x1, wv.y, acc1.y);
            acc1.z = fmaf(x1, wv.z, acc1.z); acc1.w = fmaf(x1, wv.w, acc1.w);
        }
        float4 bb = reinterpret_cast<const float4*>(bt)[lane];
        acc0.x += bb.x; acc0.y += bb.y; acc0.z += bb.z; acc0.w += bb.w;
        acc1.x += bb.x; acc1.y += bb.y; acc1.z += bb.z; acc1.w += bb.w;
        reinterpret_cast<float4*>(g_tf)[(size_t)(i0 + 2 * w) * 32 + lane] = acc0;
        reinterpret_cast<float4*>(g_tf)[(size_t)(i0 + 2 * w + 1) * 32 + lane] = acc1;

        // ---------------- per-row distance min/max (2 rows per warp) --------
        #pragma unroll
        for (int r2 = 0; r2 < 2; r2++) {
            const int i = i0 + 2 * w + r2;
            const int b = seg_res[i];
            const int as = lowerb(seg_atom, NA, b);
            const int ae = lowerb(seg_atom, NA, b + 1);
            const float px = tpos[3 * i], py = tpos[3 * i + 1], pz = tpos[3 * i + 2];
            float mn = INFINITY, mx = 0.0f;
            for (int j = as + lane; j < ae; j += 32) {
                float dx = px - dpos[3 * j];
                float dy = py - dpos[3 * j + 1];
                float dz = pz - dpos[3 * j + 2];
                float d = sqrtf(dx * dx + dy * dy + dz * dz);
                mn = fminf(mn, d); mx = fmaxf(mx, d);
            }
            #pragma unroll
            for (int o = 16; o; o >>= 1) {
                mn = fminf(mn, __shfl_xor_sync(0xFFFFFFFFu, mn, o));
                mx = fmaxf(mx, __shfl_xor_sync(0xFFFFFFFFu, mx, o));
            }
            if (lane == 0) { g_rowmin[i] = mn; g_rowmax[i] = mx; }
        }
    } else {
        // ---------------- df GEMM: 8 rows x 128 cols, warp per row ----------
        const int i0 = (blockIdx.x - NTF) * 8;
        const float4* src = reinterpret_cast<const float4*>(dfeat + (size_t)i0 * DD);
        float4* dst = reinterpret_cast<float4*>(sA);
        for (int idx = t; idx < 8 * DD / 4; idx += 256) dst[idx] = src[idx];
        __syncthreads();

        const float* arow = sA + w * DD;
        const float4* W4 = reinterpret_cast<const float4*>(Wd);
        float4 acc = make_float4(0.f, 0.f, 0.f, 0.f);
        #pragma unroll 8
        for (int k = 0; k < DD; k++) {
            float4 wv = W4[k * 32 + lane];
            float x = arow[k];
            acc.x = fmaf(x, wv.x, acc.x); acc.y = fmaf(x, wv.y, acc.y);
            acc.z = fmaf(x, wv.z, acc.z); acc.w = fmaf(x, wv.w, acc.w);
        }
        float4 bb = reinterpret_cast<const float4*>(bd)[lane];
        acc.x += bb.x; acc.y += bb.y; acc.z += bb.z; acc.w += bb.w;
        reinterpret_cast<float4*>(g_df)[(size_t)(i0 + w) * 32 + lane] = acc;
    }

    // ---------------- last-block: segment reduce + ranges + finalize --------
    __threadfence();
    __syncthreads();
    if (t == 0) {
        int c = atomicAdd(&g_count, 1);
        isLast = (c == NTF + NDF - 1);
    }
    __syncthreads();
    if (isLast) {
        if (t < B) {
            s_mn[t] = 0x7F800000;  // +inf bits (all values nonneg -> int order ok)
            s_mx[t] = 0;           // 0.0f
            s_as[t] = NA; s_ae[t] = 0;
        }
        __syncthreads();
        for (int i = t; i < NR; i += 256) {
            int b = seg_res[i];
            atomicMin(&s_mn[b], __float_as_int(g_rowmin[i]));
            atomicMax(&s_mx[b], __float_as_int(g_rowmax[i]));
        }
        for (int j = t; j < NA; j += 256) {
            int s = seg_atom[j];
            atomicMin(&s_as[s], j);
            atomicMax(&s_ae[s], j + 1);
        }
        __syncthreads();
        if (t < B) {
            float dmin = __int_as_float(s_mn[t]);
            float dmax = __int_as_float(s_mx[t]);
            if (!isfinite(dmin)) dmin = 0.0f;
            float den = (dmax > dmin) ? (dmax - dmin) : 1.0f;
            g_dminf[t] = dmin;
            g_invden[t] = 1.0f / den;
            g_as[t] = s_as[t];
            g_ae[t] = s_ae[t];
        }
        if (t == 0) g_count = 0;  // reset for next launch (graph replay safe)
    }
}

// ---------------- Kernel C: main streaming write ------------------------------
__global__ void __launch_bounds__(256) k_main(const int* __restrict__ seg_res,
                                              const float* __restrict__ tpos,
                                              const float* __restrict__ dpos,
                                              float* __restrict__ out) {
    const int i = blockIdx.x;
    const int b = seg_res[i];
    const int as = g_as[b], ae = g_ae[b];

    __shared__ float s_tf[H];
    __shared__ float s_dn[NA];

    if (threadIdx.x < H) s_tf[threadIdx.x] = g_tf[i * H + threadIdx.x];

    const float px = tpos[3 * i], py = tpos[3 * i + 1], pz = tpos[3 * i + 2];
    const float dmin = g_dminf[b], inv = g_invden[b];
    for (int j = as + (int)threadIdx.x; j < ae; j += 256) {
        float dx = px - dpos[3 * j];
        float dy = py - dpos[3 * j + 1];
        float dz = pz - dpos[3 * j + 2];
        s_dn[j - as] = (sqrtf(dx * dx + dy * dy + dz * dz) - dmin) * inv;
    }
    __syncthreads();

    float4* out4 = reinterpret_cast<float4*>(out) + (size_t)i * (NA * H / 4);
    const float4 z4 = make_float4(0.f, 0.f, 0.f, 0.f);

    // left zero stripe
    const int nl = as * (H / 4);
    for (int idx = threadIdx.x; idx < nl; idx += 256) __stcs(&out4[idx], z4);

    // right zero stripe
    const int nr = (NA - ae) * (H / 4);
    float4* outr = out4 + ae * (H / 4);
    for (int idx = threadIdx.x; idx < nr; idx += 256) __stcs(&outr[idx], z4);

    // middle: tanh(tf - df + dnorm)
    const int nm = (ae - as) * (H / 4);
    const float4* df4 = reinterpret_cast<const float4*>(g_df);
    const float4* tf4 = reinterpret_cast<const float4*>(s_tf);
    float4* outm = out4 + as * (H / 4);
    for (int idx = threadIdx.x; idx < nm; idx += 256) {
        const int jo = idx >> 5;
        const int q  = idx & 31;
        const float dn = s_dn[jo];
        const float4 tv = tf4[q];
        const float4 dv = df4[(size_t)(as + jo) * (H / 4) + q];
        float4 r;
        r.x = tanhf(tv.x - dv.x + dn);
        r.y = tanhf(tv.y - dv.y + dn);
        r.z = tanhf(tv.z - dv.z + dn);
        r.w = tanhf(tv.w - dv.w + dn);
        __stcs(&outm[idx], r);
    }
}

// ---------------- launch -------------------------------------------------------
extern "C" void kernel_launch(void* const* d_in, const int* in_sizes, int n_in,
                              void* d_out, int out_size) {
    const float* target_feature = (const float*)d_in[0];
    const float* drug_feature   = (const float*)d_in[1];
    const float* target_pos     = (const float*)d_in[2];
    const float* drug_pos       = (const float*)d_in[3];
    const float* Wt             = (const float*)d_in[4];
    const float* bt             = (const float*)d_in[5];
    const float* Wd             = (const float*)d_in[6];
    const float* bd             = (const float*)d_in[7];
    const int*   seg_res        = (const int*)d_in[8];
    const int*   seg_atom       = (const int*)d_in[9];
    float* out = (float*)d_out;

    kA<<<NTF + NDF, 256>>>(target_feature, Wt, bt,
                           drug_feature, Wd, bd,
                           target_pos, drug_pos, seg_res, seg_atom);
    k_main<<<NR, 256>>>(seg_res, target_pos, drug_pos, out);
}

// round 3
// speedup vs baseline: 1.5007x; 1.0971x over previous
#include <cuda_runtime.h>
#include <math.h>
#include <stdint.h>

#define NR 3200
#define NA 320
#define TD 512
#define DD 128
#define H  128
#define B  8

#define NTF 200   // tf GEMM blocks, 16 rows each
#define NDF 40    // df GEMM blocks, 8 rows each
#define KT  64    // k-tile for Wt staging

// dynamic smem: max(tf: 16*512 + 64*128, df: 128*128 + 8*128) floats
#define DYN_FLOATS (DD * H + 8 * DD)     // 17408 floats = 68 KB
#define DYN_BYTES  (DYN_FLOATS * 4)

// ---------------- scratch (device globals) ----------------------------------
__device__ float g_tf[NR * H];
__device__ float g_df[NA * H];
__device__ float g_rowmin[NR];
__device__ float g_rowmax[NR];
__device__ int   g_as[B];
__device__ int   g_ae[B];
__device__ float g_dminf[B];
__device__ float g_invden[B];
__device__ int   g_count = 0;   // last-block counter, self-resetting

__device__ __forceinline__ int lowerb(const int* __restrict__ a, int n, int key) {
    int lo = 0, hi = n;
    while (lo < hi) { int m = (lo + hi) >> 1; if (a[m] < key) lo = m + 1; else hi = m; }
    return lo;
}

// ---------------- Kernel A: tf GEMM + df GEMM + row dist min/max + reduce ----
__global__ void __launch_bounds__(256) kA(const float* __restrict__ tfeat,
                                          const float* __restrict__ Wt,
                                          const float* __restrict__ bt,
                                          const float* __restrict__ dfeat,
                                          const float* __restrict__ Wd,
                                          const float* __restrict__ bd,
                                          const float* __restrict__ tpos,
                                          const float* __restrict__ dpos,
                                          const int* __restrict__ seg_res,
                                          const int* __restrict__ seg_atom) {
    extern __shared__ float buf[];
    __shared__ int   s_mn[B], s_mx[B], s_as[B], s_ae[B];
    __shared__ bool  isLast;

    const int t = threadIdx.x;
    const int w = t >> 5, lane = t & 31;

    if (blockIdx.x < NTF) {
        // ---------------- tf GEMM: 16 rows x 128 cols, Wt k-tiled in smem ----
        float* sA = buf;                 // 16*512 floats
        float* sW = buf + 16 * TD;       // 64*128 floats
        float4* sW4 = reinterpret_cast<float4*>(sW);

        const int i0 = blockIdx.x * 16;
        {
            const float4* src = reinterpret_cast<const float4*>(tfeat + (size_t)i0 * TD);
            float4* dst = reinterpret_cast<float4*>(sA);
            #pragma unroll
            for (int idx = t; idx < 16 * TD / 4; idx += 256) dst[idx] = src[idx];
        }

        const float* a0 = sA + (2 * w) * TD;
        const float* a1 = sA + (2 * w + 1) * TD;
        const float4* W4 = reinterpret_cast<const float4*>(Wt);  // [TD][32] float4
        float4 acc0 = make_float4(0.f, 0.f, 0.f, 0.f);
        float4 acc1 = make_float4(0.f, 0.f, 0.f, 0.f);

        for (int kt = 0; kt < TD; kt += KT) {
            __syncthreads();  // previous tile consumed / A tile ready
            #pragma unroll
            for (int idx = t; idx < KT * H / 4; idx += 256)
                sW4[idx] = W4[(size_t)kt * (H / 4) + idx];
            __syncthreads();
            #pragma unroll 8
            for (int k = 0; k < KT; k++) {
                float4 wv = sW4[k * 32 + lane];
                float x0 = a0[kt + k], x1 = a1[kt + k];
                acc0.x = fmaf(x0, wv.x, acc0.x); acc0.y = fmaf(x0, wv.y, acc0.y);
                acc0.z = fmaf(x0, wv.z, acc0.z); acc0.w = fmaf(x0, wv.w, acc0.w);
                acc1.x = fmaf(x1, wv.x, acc1.x); acc1.y = fmaf(x1, wv.y, acc1.y);
                acc1.z = fmaf(x1, wv.z, acc1.z); acc1.w = fmaf(x1, wv.w, acc1.w);
            }
        }
        float4 bb = reinterpret_cast<const float4*>(bt)[lane];
        acc0.x += bb.x; acc0.y += bb.y; acc0.z += bb.z; acc0.w += bb.w;
        acc1.x += bb.x; acc1.y += bb.y; acc1.z += bb.z; acc1.w += bb.w;
        reinterpret_cast<float4*>(g_tf)[(size_t)(i0 + 2 * w) * 32 + lane] = acc0;
        reinterpret_cast<float4*>(g_tf)[(size_t)(i0 + 2 * w + 1) * 32 + lane] = acc1;

        // ---------------- per-row distance min/max (2 rows per warp) --------
        #pragma unroll
        for (int r2 = 0; r2 < 2; r2++) {
            const int i = i0 + 2 * w + r2;
            const int b = seg_res[i];
            const int as = lowerb(seg_atom, NA, b);
            const int ae = lowerb(seg_atom, NA, b + 1);
            const float px = tpos[3 * i], py = tpos[3 * i + 1], pz = tpos[3 * i + 2];
            float mn = INFINITY, mx = 0.0f;
            for (int j = as + lane; j < ae; j += 32) {
                float dx = px - dpos[3 * j];
                float dy = py - dpos[3 * j + 1];
                float dz = pz - dpos[3 * j + 2];
                float d = sqrtf(dx * dx + dy * dy + dz * dz);
                mn = fminf(mn, d); mx = fmaxf(mx, d);
            }
            #pragma unroll
            for (int o = 16; o; o >>= 1) {
                mn = fminf(mn, __shfl_xor_sync(0xFFFFFFFFu, mn, o));
                mx = fmaxf(mx, __shfl_xor_sync(0xFFFFFFFFu, mx, o));
            }
            if (lane == 0) { g_rowmin[i] = mn; g_rowmax[i] = mx; }
        }
    } else {
        // ---------------- df GEMM: 8 rows, Wd fully staged in smem ----------
        float* sWd = buf;                // 128*128 floats (64 KB)
        float* sAd = buf + DD * H;       // 8*128 floats
        float4* sWd4 = reinterpret_cast<float4*>(sWd);

        const int i0 = (blockIdx.x - NTF) * 8;
        {
            const float4* srcW = reinterpret_cast<const float4*>(Wd);
            #pragma unroll
            for (int idx = t; idx < DD * H / 4; idx += 256) sWd4[idx] = srcW[idx];
            const float4* srcA = reinterpret_cast<const float4*>(dfeat + (size_t)i0 * DD);
            float4* dstA = reinterpret_cast<float4*>(sAd);
            for (int idx = t; idx < 8 * DD / 4; idx += 256) dstA[idx] = srcA[idx];
        }
        __syncthreads();

        const float* arow = sAd + w * DD;
        float4 acc = make_float4(0.f, 0.f, 0.f, 0.f);
        #pragma unroll 8
        for (int k = 0; k < DD; k++) {
            float4 wv = sWd4[k * 32 + lane];
            float x = arow[k];
            acc.x = fmaf(x, wv.x, acc.x); acc.y = fmaf(x, wv.y, acc.y);
            acc.z = fmaf(x, wv.z, acc.z); acc.w = fmaf(x, wv.w, acc.w);
        }
        float4 bb = reinterpret_cast<const float4*>(bd)[lane];
        acc.x += bb.x; acc.y += bb.y; acc.z += bb.z; acc.w += bb.w;
        reinterpret_cast<float4*>(g_df)[(size_t)(i0 + w) * 32 + lane] = acc;
    }

    // ---------------- last-block: segment reduce + ranges + finalize --------
    __threadfence();
    __syncthreads();
    if (t == 0) {
        int c = atomicAdd(&g_count, 1);
        isLast = (c == NTF + NDF - 1);
    }
    __syncthreads();
    if (isLast) {
        if (t < B) {
            s_mn[t] = 0x7F800000;  // +inf bits
            s_mx[t] = 0;
            s_as[t] = NA; s_ae[t] = 0;
        }
        __syncthreads();
        for (int i = t; i < NR; i += 256) {
            int b = seg_res[i];
            atomicMin(&s_mn[b], __float_as_int(g_rowmin[i]));
            atomicMax(&s_mx[b], __float_as_int(g_rowmax[i]));
        }
        for (int j = t; j < NA; j += 256) {
            int s = seg_atom[j];
            atomicMin(&s_as[s], j);
            atomicMax(&s_ae[s], j + 1);
        }
        __syncthreads();
        if (t < B) {
            float dmin = __int_as_float(s_mn[t]);
            float dmax = __int_as_float(s_mx[t]);
            if (!isfinite(dmin)) dmin = 0.0f;
            float den = (dmax > dmin) ? (dmax - dmin) : 1.0f;
            g_dminf[t] = dmin;
            g_invden[t] = 1.0f / den;
            g_as[t] = s_as[t];
            g_ae[t] = s_ae[t];
        }
        if (t == 0) g_count = 0;  // reset for graph replay
    }
}

// ---------------- Kernel C: main streaming write ------------------------------
__global__ void __launch_bounds__(256) k_main(const int* __restrict__ seg_res,
                                              const float* __restrict__ tpos,
                                              const float* __restrict__ dpos,
                                              float* __restrict__ out) {
    const int i = blockIdx.x;
    const int b = seg_res[i];
    const int as = g_as[b], ae = g_ae[b];

    __shared__ float s_tf[H];
    __shared__ float s_dn[NA];

    if (threadIdx.x < H) s_tf[threadIdx.x] = g_tf[i * H + threadIdx.x];

    const float px = tpos[3 * i], py = tpos[3 * i + 1], pz = tpos[3 * i + 2];
    const float dmin = g_dminf[b], inv = g_invden[b];
    for (int j = as + (int)threadIdx.x; j < ae; j += 256) {
        float dx = px - dpos[3 * j];
        float dy = py - dpos[3 * j + 1];
        float dz = pz - dpos[3 * j + 2];
        s_dn[j - as] = (sqrtf(dx * dx + dy * dy + dz * dz) - dmin) * inv;
    }
    __syncthreads();

    float4* out4 = reinterpret_cast<float4*>(out) + (size_t)i * (NA * H / 4);
    const float4 z4 = make_float4(0.f, 0.f, 0.f, 0.f);

    const int nl = as * (H / 4);
    for (int idx = threadIdx.x; idx < nl; idx += 256) __stcs(&out4[idx], z4);

    const int nr = (NA - ae) * (H / 4);
    float4* outr = out4 + ae * (H / 4);
    for (int idx = threadIdx.x; idx < nr; idx += 256) __stcs(&outr[idx], z4);

    const int nm = (ae - as) * (H / 4);
    const float4* df4 = reinterpret_cast<const float4*>(g_df);
    const float4* tf4 = reinterpret_cast<const float4*>(s_tf);
    float4* outm = out4 + as * (H / 4);
    for (int idx = threadIdx.x; idx < nm; idx += 256) {
        const int jo = idx >> 5;
        const int q  = idx & 31;
        const float dn = s_dn[jo];
        const float4 tv = tf4[q];
        const float4 dv = df4[(size_t)(as + jo) * (H / 4) + q];
        float4 r;
        r.x = tanhf(tv.x - dv.x + dn);
        r.y = tanhf(tv.y - dv.y + dn);
        r.z = tanhf(tv.z - dv.z + dn);
        r.w = tanhf(tv.w - dv.w + dn);
        __stcs(&outm[idx], r);
    }
}

// ---------------- launch -------------------------------------------------------
extern "C" void kernel_launch(void* const* d_in, const int* in_sizes, int n_in,
                              void* d_out, int out_size) {
    const float* target_feature = (const float*)d_in[0];
    const float* drug_feature   = (const float*)d_in[1];
    const float* target_pos     = (const float*)d_in[2];
    const float* drug_pos       = (const float*)d_in[3];
    const float* Wt             = (const float*)d_in[4];
    const float* bt             = (const float*)d_in[5];
    const float* Wd             = (const float*)d_in[6];
    const float* bd             = (const float*)d_in[7];
    const int*   seg_res        = (const int*)d_in[8];
    const int*   seg_atom       = (const int*)d_in[9];
    float* out = (float*)d_out;

    cudaFuncSetAttribute(kA, cudaFuncAttributeMaxDynamicSharedMemorySize, DYN_BYTES);

    kA<<<NTF + NDF, 256, DYN_BYTES>>>(target_feature, Wt, bt,
                                      drug_feature, Wd, bd,
                                      target_pos, drug_pos, seg_res, seg_atom);
    k_main<<<NR, 256>>>(seg_res, target_pos, drug_pos, out);
}

// round 4
// speedup vs baseline: 1.7590x; 1.1721x over previous
#include <cuda_runtime.h>
#include <math.h>
#include <stdint.h>

#define NR 3200
#define NA 320
#define TD 512
#define DD 128
#define H  128
#define B  8

#define NTF 200              // tf GEMM blocks, 16 rows each
#define NDF 40               // df GEMM blocks, 8 rows each
#define NGEMM (NTF + NDF)
#define NB  444              // one full wave: 148 SMs x 3 blocks
#define KT  64               // k-tile for Wt staging

// dynamic smem: max(tf: 16*512 + 64*128, df: 128*128 + 8*128) floats = 68 KB
#define DYN_FLOATS (DD * H + 8 * DD)
#define DYN_BYTES  (DYN_FLOATS * 4)

// ---------------- scratch (device globals) ----------------------------------
__device__ float g_tf[NR * H];
__device__ float g_df[NA * H];
__device__ float g_rowmin[NR];
__device__ float g_rowmax[NR];
__device__ float g_dminf[B];
__device__ float g_invden[B];
__device__ int   g_gemm_done = 0;
__device__ int   g_ready     = 0;
__device__ int   g_zrow      = 0;
__device__ int   g_trow      = 0;
__device__ int   g_fin       = 0;

__device__ __forceinline__ int lowerb(const int* __restrict__ a, int n, int key) {
    int lo = 0, hi = n;
    while (lo < hi) { int m = (lo + hi) >> 1; if (a[m] < key) lo = m + 1; else hi = m; }
    return lo;
}

// ---------------- fused persistent kernel ------------------------------------
__global__ void __launch_bounds__(256, 3)
k_fused(const float* __restrict__ tfeat,
        const float* __restrict__ Wt,
        const float* __restrict__ bt,
        const float* __restrict__ dfeat,
        const float* __restrict__ Wd,
        const float* __restrict__ bd,
        const float* __restrict__ tpos,
        const float* __restrict__ dpos,
        const int* __restrict__ seg_res,
        const int* __restrict__ seg_atom,
        float* __restrict__ out) {
    extern __shared__ float buf[];
    __shared__ int  s_as8[B], s_ae8[B];
    __shared__ int  s_mn[B], s_mx[B];
    __shared__ int  s_claim;
    __shared__ bool isLast;

    const int t = threadIdx.x;
    const int w = t >> 5, lane = t & 31;
    const int bid = blockIdx.x;

    // atom ranges per segment (seg_atom sorted): computed once per block
    if (t < B) {
        s_as8[t] = lowerb(seg_atom, NA, t);
        s_ae8[t] = lowerb(seg_atom, NA, t + 1);
    }
    __syncthreads();

    // ======================= GEMM work (blocks 0..NGEMM-1) ===================
    if (bid < NTF) {
        // ---- tf GEMM: 16 rows x 128 cols, Wt k-tiled in smem ----
        float* sA = buf;                 // 16*512 floats
        float* sW = buf + 16 * TD;       // 64*128 floats
        float4* sW4 = reinterpret_cast<float4*>(sW);

        const int i0 = bid * 16;
        {
            const float4* src = reinterpret_cast<const float4*>(tfeat + (size_t)i0 * TD);
            float4* dst = reinterpret_cast<float4*>(sA);
            #pragma unroll
            for (int idx = t; idx < 16 * TD / 4; idx += 256) dst[idx] = src[idx];
        }

        const float* a0 = sA + (2 * w) * TD;
        const float* a1 = sA + (2 * w + 1) * TD;
        const float4* W4 = reinterpret_cast<const float4*>(Wt);
        float4 acc0 = make_float4(0.f, 0.f, 0.f, 0.f);
        float4 acc1 = make_float4(0.f, 0.f, 0.f, 0.f);

        for (int kt = 0; kt < TD; kt += KT) {
            __syncthreads();
            #pragma unroll
            for (int idx = t; idx < KT * H / 4; idx += 256)
                sW4[idx] = W4[(size_t)kt * (H / 4) + idx];
            __syncthreads();
            #pragma unroll 8
            for (int k = 0; k < KT; k++) {
                float4 wv = sW4[k * 32 + lane];
                float x0 = a0[kt + k], x1 = a1[kt + k];
                acc0.x = fmaf(x0, wv.x, acc0.x); acc0.y = fmaf(x0, wv.y, acc0.y);
                acc0.z = fmaf(x0, wv.z, acc0.z); acc0.w = fmaf(x0, wv.w, acc0.w);
                acc1.x = fmaf(x1, wv.x, acc1.x); acc1.y = fmaf(x1, wv.y, acc1.y);
                acc1.z = fmaf(x1, wv.z, acc1.z); acc1.w = fmaf(x1, wv.w, acc1.w);
            }
        }
        float4 bb = reinterpret_cast<const float4*>(bt)[lane];
        acc0.x += bb.x; acc0.y += bb.y; acc0.z += bb.z; acc0.w += bb.w;
        acc1.x += bb.x; acc1.y += bb.y; acc1.z += bb.z; acc1.w += bb.w;
        reinterpret_cast<float4*>(g_tf)[(size_t)(i0 + 2 * w) * 32 + lane] = acc0;
        reinterpret_cast<float4*>(g_tf)[(size_t)(i0 + 2 * w + 1) * 32 + lane] = acc1;

        // ---- per-row distance min/max (2 rows per warp) ----
        #pragma unroll
        for (int r2 = 0; r2 < 2; r2++) {
            const int i = i0 + 2 * w + r2;
            const int b = seg_res[i];
            const int as = s_as8[b], ae = s_ae8[b];
            const float px = tpos[3 * i], py = tpos[3 * i + 1], pz = tpos[3 * i + 2];
            float mn = INFINITY, mx = 0.0f;
            for (int j = as + lane; j < ae; j += 32) {
                float dx = px - dpos[3 * j];
                float dy = py - dpos[3 * j + 1];
                float dz = pz - dpos[3 * j + 2];
                float d = sqrtf(dx * dx + dy * dy + dz * dz);
                mn = fminf(mn, d); mx = fmaxf(mx, d);
            }
            #pragma unroll
            for (int o = 16; o; o >>= 1) {
                mn = fminf(mn, __shfl_xor_sync(0xFFFFFFFFu, mn, o));
                mx = fmaxf(mx, __shfl_xor_sync(0xFFFFFFFFu, mx, o));
            }
            if (lane == 0) { g_rowmin[i] = mn; g_rowmax[i] = mx; }
        }
    } else if (bid < NGEMM) {
        // ---- df GEMM: 8 rows, Wd fully staged in smem ----
        float* sWd = buf;                // 128*128 floats
        float* sAd = buf + DD * H;       // 8*128 floats
        float4* sWd4 = reinterpret_cast<float4*>(sWd);

        const int i0 = (bid - NTF) * 8;
        {
            const float4* srcW = reinterpret_cast<const float4*>(Wd);
            #pragma unroll
            for (int idx = t; idx < DD * H / 4; idx += 256) sWd4[idx] = srcW[idx];
            const float4* srcA = reinterpret_cast<const float4*>(dfeat + (size_t)i0 * DD);
            float4* dstA = reinterpret_cast<float4*>(sAd);
            for (int idx = t; idx < 8 * DD / 4; idx += 256) dstA[idx] = srcA[idx];
        }
        __syncthreads();

        const float* arow = sAd + w * DD;
        float4 acc = make_float4(0.f, 0.f, 0.f, 0.f);
        #pragma unroll 8
        for (int k = 0; k < DD; k++) {
            float4 wv = sWd4[k * 32 + lane];
            float x = arow[k];
            acc.x = fmaf(x, wv.x, acc.x); acc.y = fmaf(x, wv.y, acc.y);
            acc.z = fmaf(x, wv.z, acc.z); acc.w = fmaf(x, wv.w, acc.w);
        }
        float4 bb = reinterpret_cast<const float4*>(bd)[lane];
        acc.x += bb.x; acc.y += bb.y; acc.z += bb.z; acc.w += bb.w;
        reinterpret_cast<float4*>(g_df)[(size_t)(i0 + w) * 32 + lane] = acc;
    }

    // -------- GEMM completion: last GEMM block reduces + releases g_ready ----
    if (bid < NGEMM) {
        __threadfence();
        __syncthreads();
        if (t == 0) isLast = (atomicAdd(&g_gemm_done, 1) == NGEMM - 1);
        __syncthreads();
        if (isLast) {
            __threadfence();  // acquire side: producers fenced before counter
            if (t < B) { s_mn[t] = 0x7F800000; s_mx[t] = 0; }
            __syncthreads();
            for (int i = t; i < NR; i += 256) {
                int b = seg_res[i];
                atomicMin(&s_mn[b], __float_as_int(__ldcg(&g_rowmin[i])));
                atomicMax(&s_mx[b], __float_as_int(__ldcg(&g_rowmax[i])));
            }
            __syncthreads();
            if (t < B) {
                float dmin = __int_as_float(s_mn[t]);
                float dmax = __int_as_float(s_mx[t]);
                if (!isfinite(dmin)) dmin = 0.0f;
                float den = (dmax > dmin) ? (dmax - dmin) : 1.0f;
                g_dminf[t] = dmin;
                g_invden[t] = 1.0f / den;
            }
            __syncthreads();
            if (t == 0) { __threadfence(); atomicExch(&g_ready, 1); }
        }
    }

    const float4 z4 = make_float4(0.f, 0.f, 0.f, 0.f);

    // ======================= Phase Z: zero stripes (work-stealing) ===========
    for (;;) {
        __syncthreads();
        if (t == 0) s_claim = atomicAdd(&g_zrow, 1);
        __syncthreads();
        const int i = s_claim;
        if (i >= NR) break;
        const int b = seg_res[i];
        const int as = s_as8[b], ae = s_ae8[b];
        float4* out4 = reinterpret_cast<float4*>(out) + (size_t)i * (NA * H / 4);

        const int nl = as * (H / 4);
        for (int idx = t; idx < nl; idx += 256) __stcs(&out4[idx], z4);

        const int nr_ = (NA - ae) * (H / 4);
        float4* outr = out4 + ae * (H / 4);
        for (int idx = t; idx < nr_; idx += 256) __stcs(&outr[idx], z4);
    }

    // ======================= wait for GEMM + reduce ===========================
    if (t == 0) {
        while (((volatile int*)&g_ready)[0] == 0) __nanosleep(128);
    }
    __syncthreads();
    __threadfence();

    // ======================= Phase T: tanh middle (work-stealing) =============
    float* s_dn = buf;        // NA floats (GEMM use of buf is over for this block)
    float* s_tf = buf + NA;   // H floats
    const float4* df4 = reinterpret_cast<const float4*>(g_df);

    for (;;) {
        __syncthreads();
        if (t == 0) s_claim = atomicAdd(&g_trow, 1);
        __syncthreads();
        const int i = s_claim;
        if (i >= NR) break;
        const int b = seg_res[i];
        const int as = s_as8[b], ae = s_ae8[b];
        if (ae <= as) continue;

        const float dmin = __ldcg(&g_dminf[b]);
        const float inv  = __ldcg(&g_invden[b]);

        if (t < H) s_tf[t] = __ldcg(&g_tf[(size_t)i * H + t]);

        const float px = tpos[3 * i], py = tpos[3 * i + 1], pz = tpos[3 * i + 2];
        for (int j = as + t; j < ae; j += 256) {
            float dx = px - dpos[3 * j];
            float dy = py - dpos[3 * j + 1];
            float dz = pz - dpos[3 * j + 2];
            s_dn[j - as] = (sqrtf(dx * dx + dy * dy + dz * dz) - dmin) * inv;
        }
        __syncthreads();

        float4* outm = reinterpret_cast<float4*>(out) + (size_t)i * (NA * H / 4) + as * (H / 4);
        const float4* tf4 = reinterpret_cast<const float4*>(s_tf);
        const int nm = (ae - as) * (H / 4);
        for (int idx = t; idx < nm; idx += 256) {
            const int jo = idx >> 5;
            const int q  = idx & 31;
            const float dn = s_dn[jo];
            const float4 tv = tf4[q];
            const float4 dv = __ldcg(&df4[(size_t)(as + jo) * (H / 4) + q]);
            float4 r;
            r.x = tanhf(tv.x - dv.x + dn);
            r.y = tanhf(tv.y - dv.y + dn);
            r.z = tanhf(tv.z - dv.z + dn);
            r.w = tanhf(tv.w - dv.w + dn);
            __stcs(&outm[idx], r);
        }
    }

    // ======================= finish: last block resets counters ===============
    __syncthreads();
    if (t == 0) {
        int c = atomicAdd(&g_fin, 1);
        if (c == NB - 1) {
            g_gemm_done = 0;
            g_ready = 0;
            g_zrow = 0;
            g_trow = 0;
            g_fin = 0;
        }
    }
}

// ---------------- launch -------------------------------------------------------
extern "C" void kernel_launch(void* const* d_in, const int* in_sizes, int n_in,
                              void* d_out, int out_size) {
    const float* target_feature = (const float*)d_in[0];
    const float* drug_feature   = (const float*)d_in[1];
    const float* target_pos     = (const float*)d_in[2];
    const float* drug_pos       = (const float*)d_in[3];
    const float* Wt             = (const float*)d_in[4];
    const float* bt             = (const float*)d_in[5];
    const float* Wd             = (const float*)d_in[6];
    const float* bd             = (const float*)d_in[7];
    const int*   seg_res        = (const int*)d_in[8];
    const int*   seg_atom       = (const int*)d_in[9];
    float* out = (float*)d_out;

    cudaFuncSetAttribute(k_fused, cudaFuncAttributeMaxDynamicSharedMemorySize, DYN_BYTES);

    k_fused<<<NB, 256, DYN_BYTES>>>(target_feature, Wt, bt,
                                    drug_feature, Wd, bd,
                                    target_pos, drug_pos,
                                    seg_res, seg_atom, out);
}